// round 1
// baseline (speedup 1.0000x reference)
#include <cuda_runtime.h>
#include <math.h>

#define Bn   16
#define Sn   512
#define Dn   1024
#define Hn   8
#define DHn  512
#define HDn  64
#define DFFn 4096
#define BSn  (Bn*Sn)   // 8192

// ---------------- scratch (static device globals; no allocation) ----------------
__device__ float g_q1[Bn*Hn*Sn*HDn];
__device__ float g_k1[Bn*Hn*Sn*HDn];
__device__ float g_v1[Bn*Hn*Sn*HDn];
__device__ float g_q2[Bn*Hn*Sn*HDn];
__device__ float g_k2[Bn*Hn*Sn*HDn];
__device__ float g_v2[Bn*Hn*Sn*HDn];
__device__ float g_av1[BSn*DHn];
__device__ float g_av2[BSn*DHn];
__device__ float g_attn[BSn*Dn];
__device__ float g_out1[BSn*Dn];
__device__ float g_hid[(size_t)BSn*DFFn];
__device__ float g_ffn[BSn*Dn];

__device__ __forceinline__ float gelu_f(float x){
    return 0.5f * x * (1.0f + erff(x * 0.70710678118654752440f));
}

// ---------------- SGEMM: C = A(MxK, lda) @ B(KxN, ldb) + bias, epilogues ----------------
// EPI 0: C[m*ldc + coff + n] = acc + bias[n]
// EPI 1: same with GELU
// EPI 2: scatter to (B,H,S,64):  C[((b*8+h)*512+s)*64+d], b=m>>9, s=m&511, h=n>>6, d=n&63
#define GBM 128
#define GBN 128
#define GBK 16

template<int EPI>
__global__ void __launch_bounds__(256) sgemm_k(
    const float* __restrict__ A, int lda,
    const float* __restrict__ Bw, int ldb,
    const float* __restrict__ bias,
    float* __restrict__ C, int ldc, int coff,
    int M, int N, int K)
{
    __shared__ float As[GBK][GBM];
    __shared__ float Bs[GBK][GBN];

    const int tid = threadIdx.x;
    const int tx = tid & 15;      // 0..15
    const int ty = tid >> 4;      // 0..15
    const int m0 = blockIdx.y * GBM;
    const int n0 = blockIdx.x * GBN;

    float acc[8][8];
    #pragma unroll
    for (int i=0;i<8;i++)
        #pragma unroll
        for (int j=0;j<8;j++) acc[i][j] = 0.f;

    for (int k0 = 0; k0 < K; k0 += GBK) {
        // load A tile (128x16) as float4 along K, transpose into As[k][m]
        #pragma unroll
        for (int it=0; it<2; it++){
            int l   = tid + it*256;         // 0..511
            int row = l >> 2;               // 0..127
            int kq  = l & 3;                // 0..3
            float4 a = *(const float4*)(A + (size_t)(m0+row)*lda + k0 + kq*4);
            As[kq*4+0][row] = a.x;
            As[kq*4+1][row] = a.y;
            As[kq*4+2][row] = a.z;
            As[kq*4+3][row] = a.w;
        }
        // load B tile (16x128) as float4 along N
        #pragma unroll
        for (int it=0; it<2; it++){
            int l  = tid + it*256;          // 0..511
            int kk = l >> 5;                // 0..15
            int nq = l & 31;                // 0..31
            *(float4*)(&Bs[kk][nq*4]) =
                *(const float4*)(Bw + (size_t)(k0+kk)*ldb + n0 + nq*4);
        }
        __syncthreads();

        #pragma unroll
        for (int kk=0; kk<GBK; kk++){
            float4 a0 = *(const float4*)(&As[kk][ty*8]);
            float4 a1 = *(const float4*)(&As[kk][ty*8+4]);
            float4 b0 = *(const float4*)(&Bs[kk][tx*8]);
            float4 b1 = *(const float4*)(&Bs[kk][tx*8+4]);
            float ar[8] = {a0.x,a0.y,a0.z,a0.w,a1.x,a1.y,a1.z,a1.w};
            float br[8] = {b0.x,b0.y,b0.z,b0.w,b1.x,b1.y,b1.z,b1.w};
            #pragma unroll
            for (int i=0;i<8;i++)
                #pragma unroll
                for (int j=0;j<8;j++)
                    acc[i][j] += ar[i]*br[j];
        }
        __syncthreads();
    }

    #pragma unroll
    for (int i=0;i<8;i++){
        int m = m0 + ty*8 + i;
        #pragma unroll
        for (int j=0;j<8;j++){
            int n = n0 + tx*8 + j;
            float v = acc[i][j] + bias[n];
            if (EPI == 1) v = gelu_f(v);
            if (EPI == 2) {
                int b = m >> 9, s = m & 511, h = n >> 6, d = n & 63;
                C[(((size_t)(b*8 + h))*512 + s)*64 + d] = v;
            } else {
                C[(size_t)m*ldc + coff + n] = v;
            }
        }
    }
}

// ---------------- attention: 1 block per (b,h,query), 128 threads ----------------
// q,k,v in (B,H,S,64); mask (B,S); extra (B,S,S); aw_out (B,H,S,S); av_out (B,S,512)
__global__ void __launch_bounds__(128) attn_k(
    const float* __restrict__ q, const float* __restrict__ k,
    const float* __restrict__ v,
    const float* __restrict__ mask, const float* __restrict__ extra,
    int mode, float* __restrict__ aw_out, float* __restrict__ av_out)
{
    __shared__ float sK[128*65];
    __shared__ float sq[64];
    __shared__ float sc[512];
    __shared__ float red[4];
    __shared__ float par[64];

    const int t  = threadIdx.x;
    const int bh = blockIdx.y;
    const int b  = bh >> 3;
    const int h  = bh & 7;
    const int i  = blockIdx.x;

    const float* qrow = q + ((size_t)bh*Sn + i)*HDn;
    if (t < 64) sq[t] = qrow[t];

    const float* kb = k + (size_t)bh*Sn*HDn;
    for (int tile=0; tile<4; tile++){
        const float* kt = kb + (size_t)tile*128*HDn;
        #pragma unroll
        for (int it=0; it<64; it++){
            int l = t + it*128;       // 0..8191
            int row = l >> 6, d = l & 63;
            sK[row*65 + d] = kt[l];
        }
        __syncthreads();
        float s = 0.f;
        #pragma unroll
        for (int d2=0; d2<64; d2++) s += sq[d2] * sK[t*65 + d2];
        sc[tile*128 + t] = s;
        __syncthreads();
    }

    // logits + softmax (4 elements per thread)
    const float* mrow = mask + (size_t)b*Sn;
    const float* erow = extra + ((size_t)b*Sn + i)*Sn;
    float lv[4];
    float lmax = -3.0e38f;
    #pragma unroll
    for (int c=0;c<4;c++){
        int j = t + c*128;
        float s = sc[j];
        float logit;
        if (mode == 0){
            logit = s*0.125f + mrow[j]*(-1.0e9f) + erow[j];
        } else {
            float w = erow[j];
            float r = 3.7182818284590452f / (1.f + expf(1.f - w));
            logit = fmaxf(s, 0.f)*r*0.125f + mrow[j]*(-1.0e9f);
        }
        lv[c] = logit;
        lmax = fmaxf(lmax, logit);
    }
    #pragma unroll
    for (int o=16;o>0;o>>=1) lmax = fmaxf(lmax, __shfl_xor_sync(0xffffffffu, lmax, o));
    if ((t & 31) == 0) red[t>>5] = lmax;
    __syncthreads();
    float gmax = fmaxf(fmaxf(red[0],red[1]), fmaxf(red[2],red[3]));
    __syncthreads();

    float lsum = 0.f;
    #pragma unroll
    for (int c=0;c<4;c++){ lv[c] = expf(lv[c] - gmax); lsum += lv[c]; }
    #pragma unroll
    for (int o=16;o>0;o>>=1) lsum += __shfl_xor_sync(0xffffffffu, lsum, o);
    if ((t & 31) == 0) red[t>>5] = lsum;
    __syncthreads();
    float gsum = red[0]+red[1]+red[2]+red[3];
    float inv = 1.f / gsum;

    float* awrow = aw_out + ((size_t)bh*Sn + i)*Sn;
    #pragma unroll
    for (int c=0;c<4;c++){
        int j = t + c*128;
        float a = lv[c]*inv;
        sc[j] = a;
        awrow[j] = a;
    }
    __syncthreads();

    // AV: out[d] = sum_j aw[j]*v[j][d]; split 512 keys over 2 half-groups
    const int d = t & 63, half = t >> 6;
    const float* vb = v + (size_t)bh*Sn*HDn;
    float acc = 0.f;
    const int j0 = half*256;
    #pragma unroll 4
    for (int j=j0; j<j0+256; j++) acc += sc[j] * vb[(size_t)j*64 + d];
    if (half) par[d] = acc;
    __syncthreads();
    if (!half) av_out[((size_t)b*Sn + i)*DHn + h*HDn + d] = acc + par[d];
}

// ---------------- fused add + LayerNorm: 1 block per row (1024) ----------------
__global__ void __launch_bounds__(256) add_ln_k(
    const float* __restrict__ a, const float* __restrict__ r,
    const float* __restrict__ g, const float* __restrict__ be,
    float* __restrict__ out)
{
    __shared__ float red[8];
    const int row = blockIdx.x;
    const int t = threadIdx.x;
    const float* ar = a + (size_t)row*Dn;
    const float* rr = r + (size_t)row*Dn;

    float vals[4];
    float s = 0.f;
    #pragma unroll
    for (int c=0;c<4;c++){
        float x = ar[t + c*256] + rr[t + c*256];
        vals[c] = x; s += x;
    }
    #pragma unroll
    for (int o=16;o>0;o>>=1) s += __shfl_xor_sync(0xffffffffu, s, o);
    if ((t & 31) == 0) red[t>>5] = s;
    __syncthreads();
    float tot = 0.f;
    #pragma unroll
    for (int w=0;w<8;w++) tot += red[w];
    float mean = tot * (1.f/1024.f);
    __syncthreads();

    float sq = 0.f;
    #pragma unroll
    for (int c=0;c<4;c++){ float dx = vals[c]-mean; sq += dx*dx; }
    #pragma unroll
    for (int o=16;o>0;o>>=1) sq += __shfl_xor_sync(0xffffffffu, sq, o);
    if ((t & 31) == 0) red[t>>5] = sq;
    __syncthreads();
    float vtot = 0.f;
    #pragma unroll
    for (int w=0;w<8;w++) vtot += red[w];
    float invstd = rsqrtf(vtot*(1.f/1024.f) + 1e-5f);

    #pragma unroll
    for (int c=0;c<4;c++){
        int dd = t + c*256;
        out[(size_t)row*Dn + dd] = (vals[c]-mean)*invstd*g[dd] + be[dd];
    }
}

// ---------------- launch ----------------
extern "C" void kernel_launch(void* const* d_in, const int* in_sizes, int n_in,
                              void* d_out, int out_size)
{
    const float* x      = (const float*)d_in[0];
    const float* mask   = (const float*)d_in[2];
    const float* adjoin = (const float*)d_in[3];
    const float* dist   = (const float*)d_in[4];
    const float* wq1=(const float*)d_in[5],  *bq1=(const float*)d_in[6];
    const float* wk1=(const float*)d_in[7],  *bk1=(const float*)d_in[8];
    const float* wv1=(const float*)d_in[9],  *bv1=(const float*)d_in[10];
    const float* wo1=(const float*)d_in[11], *bo1=(const float*)d_in[12];
    const float* wq2=(const float*)d_in[13], *bq2=(const float*)d_in[14];
    const float* wk2=(const float*)d_in[15], *bk2=(const float*)d_in[16];
    const float* wv2=(const float*)d_in[17], *bv2=(const float*)d_in[18];
    const float* wo2=(const float*)d_in[19], *bo2=(const float*)d_in[20];
    const float* wff1=(const float*)d_in[21], *bff1=(const float*)d_in[22];
    const float* wff2=(const float*)d_in[23], *bff2=(const float*)d_in[24];
    const float* ln1g=(const float*)d_in[25], *ln1b=(const float*)d_in[26];
    const float* ln2g=(const float*)d_in[27], *ln2b=(const float*)d_in[28];

    float* out2 = (float*)d_out;                         // (B,S,D)
    float* aw_l = out2 + (size_t)BSn*Dn;                 // (B,H,S,S)
    float* aw_g = aw_l + (size_t)Bn*Hn*Sn*Sn;            // (B,H,S,S)

    float *q1,*k1,*v1,*q2,*k2,*v2,*av1,*av2,*attn,*out1,*hid,*ffn;
    cudaGetSymbolAddress((void**)&q1, g_q1);
    cudaGetSymbolAddress((void**)&k1, g_k1);
    cudaGetSymbolAddress((void**)&v1, g_v1);
    cudaGetSymbolAddress((void**)&q2, g_q2);
    cudaGetSymbolAddress((void**)&k2, g_k2);
    cudaGetSymbolAddress((void**)&v2, g_v2);
    cudaGetSymbolAddress((void**)&av1, g_av1);
    cudaGetSymbolAddress((void**)&av2, g_av2);
    cudaGetSymbolAddress((void**)&attn, g_attn);
    cudaGetSymbolAddress((void**)&out1, g_out1);
    cudaGetSymbolAddress((void**)&hid, g_hid);
    cudaGetSymbolAddress((void**)&ffn, g_ffn);

    dim3 g512(DHn/GBN, BSn/GBM);      // (4, 64)

    // QKV projections -> (B,H,S,64)
    sgemm_k<2><<<g512,256>>>(x,       Dn, wq1, DHn, bq1, q1, 0,0, BSn, DHn, DHn);
    sgemm_k<2><<<g512,256>>>(x,       Dn, wk1, DHn, bk1, k1, 0,0, BSn, DHn, DHn);
    sgemm_k<2><<<g512,256>>>(x,       Dn, wv1, DHn, bv1, v1, 0,0, BSn, DHn, DHn);
    sgemm_k<2><<<g512,256>>>(x + DHn, Dn, wq2, DHn, bq2, q2, 0,0, BSn, DHn, DHn);
    sgemm_k<2><<<g512,256>>>(x + DHn, Dn, wk2, DHn, bk2, k2, 0,0, BSn, DHn, DHn);
    sgemm_k<2><<<g512,256>>>(x + DHn, Dn, wv2, DHn, bv2, v2, 0,0, BSn, DHn, DHn);

    // attention (writes aw directly into d_out)
    dim3 ag(Sn, Bn*Hn);
    attn_k<<<ag,128>>>(q1,k1,v1, mask, adjoin, 0, aw_l, av1);
    attn_k<<<ag,128>>>(q2,k2,v2, mask, dist,   1, aw_g, av2);

    // output projections -> concat into g_attn (B,S,1024)
    sgemm_k<0><<<g512,256>>>(av1, DHn, wo1, DHn, bo1, attn, Dn, 0,   BSn, DHn, DHn);
    sgemm_k<0><<<g512,256>>>(av2, DHn, wo2, DHn, bo2, attn, Dn, DHn, BSn, DHn, DHn);

    // LN1(x + attn)
    add_ln_k<<<BSn,256>>>(x, attn, ln1g, ln1b, out1);

    // FFN
    dim3 gff1(DFFn/GBN, BSn/GBM);     // (32, 64)
    sgemm_k<1><<<gff1,256>>>(out1, Dn, wff1, DFFn, bff1, hid, DFFn, 0, BSn, DFFn, Dn);
    dim3 gff2(Dn/GBN, BSn/GBM);       // (8, 64)
    sgemm_k<0><<<gff2,256>>>(hid, DFFn, wff2, Dn, bff2, ffn, Dn, 0, BSn, Dn, DFFn);

    // LN2(out1 + ffn) -> out2
    add_ln_k<<<BSn,256>>>(out1, ffn, ln2g, ln2b, out2);
}

// round 6
// speedup vs baseline: 3.5648x; 3.5648x over previous
#include <cuda_runtime.h>
#include <math.h>
#include <stdint.h>

#define Bn   16
#define Sn   512
#define Dn   1024
#define Hn   8
#define DHn  512
#define HDn  64
#define DFFn 4096
#define BSn  (Bn*Sn)   // 8192

// ---------------- scratch (static device globals; no allocation) ----------------
__device__ float g_q1[Bn*Hn*Sn*HDn];
__device__ float g_k1[Bn*Hn*Sn*HDn];   // stored transposed: (B,H,64,S)
__device__ float g_v1[Bn*Hn*Sn*HDn];
__device__ float g_q2[Bn*Hn*Sn*HDn];
__device__ float g_k2[Bn*Hn*Sn*HDn];   // transposed
__device__ float g_v2[Bn*Hn*Sn*HDn];
__device__ float g_av1[BSn*DHn];
__device__ float g_av2[BSn*DHn];
__device__ float g_attn[BSn*Dn];
__device__ float g_out1[BSn*Dn];
__device__ float g_hid[(size_t)BSn*DFFn];
__device__ float g_ffn[BSn*Dn];

__device__ __forceinline__ float gelu_f(float x){
    return 0.5f * x * (1.0f + erff(x * 0.70710678118654752440f));
}
__device__ __forceinline__ unsigned f2tf(float x){
    unsigned u; asm("cvt.rna.tf32.f32 %0, %1;" : "=r"(u) : "f"(x)); return u;
}

// =================== TF32 tensor-core GEMM core ===================
// Block tile: 128 x BN x 16.  Warp tile 64x32 (m16n8k8 frags: 4x4).
// A is m-major in smem [128][20]; B is k-major [16][BN+8].
// A pre-offset by m0*lda, B pre-offset by n0.
#define PADA 20

template<int BN>
__device__ __forceinline__ void gemm_core_tf32(
    const float* __restrict__ A, int lda,
    const float* __restrict__ Bw, int ldb,
    int K,
    unsigned (*As)[PADA], unsigned (*Bs)[BN+8],
    float (&acc)[4][4][4])
{
    constexpr int NW = BN/32;         // warps along n
    constexpr int NT = 64*NW;         // threads
    const int tid  = threadIdx.x;
    const int lane = tid & 31;
    const int warp = tid >> 5;
    const int wy = warp / NW;
    const int wx = warp % NW;
    const int lg = lane >> 2;         // 0..7
    const int lt = lane & 3;          // 0..3

    for (int k0 = 0; k0 < K; k0 += 16) {
        // ---- A tile: 128 rows x 16 k ----
        #pragma unroll
        for (int it = 0; it < 512/NT; it++) {
            int l = tid + it*NT;
            int row = l >> 2, kq = l & 3;
            float4 a = *(const float4*)(A + (size_t)row*lda + k0 + kq*4);
            uint4 t;
            t.x = f2tf(a.x); t.y = f2tf(a.y); t.z = f2tf(a.z); t.w = f2tf(a.w);
            *(uint4*)(&As[row][kq*4]) = t;
        }
        // ---- B tile: 16 k x BN ----
        #pragma unroll
        for (int it = 0; it < (4*BN)/NT; it++) {
            int l = tid + it*NT;
            int kk = l / (BN/4);
            int nq = l % (BN/4);
            float4 b = *(const float4*)(Bw + (size_t)(k0+kk)*ldb + nq*4);
            uint4 t;
            t.x = f2tf(b.x); t.y = f2tf(b.y); t.z = f2tf(b.z); t.w = f2tf(b.w);
            *(uint4*)(&Bs[kk][nq*4]) = t;
        }
        __syncthreads();

        #pragma unroll
        for (int ks = 0; ks < 2; ks++) {
            const int kb = ks*8;
            unsigned af[4][4], bf[4][2];
            #pragma unroll
            for (int fm=0; fm<4; fm++){
                int rb = wy*64 + fm*16 + lg;
                af[fm][0] = As[rb  ][kb+lt];
                af[fm][1] = As[rb+8][kb+lt];
                af[fm][2] = As[rb  ][kb+4+lt];
                af[fm][3] = As[rb+8][kb+4+lt];
            }
            #pragma unroll
            for (int fn=0; fn<4; fn++){
                int cb = wx*32 + fn*8 + lg;
                bf[fn][0] = Bs[kb+lt  ][cb];
                bf[fn][1] = Bs[kb+4+lt][cb];
            }
            #pragma unroll
            for (int fm=0; fm<4; fm++)
                #pragma unroll
                for (int fn=0; fn<4; fn++)
                    asm volatile(
                        "mma.sync.aligned.m16n8k8.row.col.f32.tf32.tf32.f32 "
                        "{%0,%1,%2,%3}, {%4,%5,%6,%7}, {%8,%9}, {%0,%1,%2,%3};"
                        : "+f"(acc[fm][fn][0]), "+f"(acc[fm][fn][1]),
                          "+f"(acc[fm][fn][2]), "+f"(acc[fm][fn][3])
                        : "r"(af[fm][0]), "r"(af[fm][1]), "r"(af[fm][2]), "r"(af[fm][3]),
                          "r"(bf[fn][0]), "r"(bf[fn][1]));
        }
        __syncthreads();
    }
}

// Epilogue coordinate helper (per lane): 4 accum values at
// rows {r, r, r+8, r+8}, cols {c, c+1, c, c+1}, r = wy*64+fm*16+lg, c = wx*32+fn*8+lt*2.

// =================== QKV: 6 batched GEMMs, scatter epilogue ===================
__global__ void __launch_bounds__(256,2) qkv_k(
    const float* __restrict__ x,
    const float* w0, const float* w1, const float* w2,
    const float* w3, const float* w4, const float* w5,
    const float* b0, const float* b1, const float* b2,
    const float* b3, const float* b4, const float* b5,
    float* o0, float* o1, float* o2, float* o3, float* o4, float* o5)
{
    __shared__ unsigned As[128][PADA];
    __shared__ unsigned Bs[16][136];

    const int z = blockIdx.z;
    const float* W; const float* bi; float* dst;
    switch (z) {
        case 0: W=w0; bi=b0; dst=o0; break;
        case 1: W=w1; bi=b1; dst=o1; break;
        case 2: W=w2; bi=b2; dst=o2; break;
        case 3: W=w3; bi=b3; dst=o3; break;
        case 4: W=w4; bi=b4; dst=o4; break;
        default:W=w5; bi=b5; dst=o5; break;
    }
    const int m0 = blockIdx.y*128, n0 = blockIdx.x*128;
    const float* A = x + (z>=3 ? DHn : 0) + (size_t)m0*Dn;
    const float* Bp = W + n0;

    float acc[4][4][4];
    #pragma unroll
    for (int i=0;i<4;i++) for (int j=0;j<4;j++) for (int r=0;r<4;r++) acc[i][j][r]=0.f;

    gemm_core_tf32<128>(A, Dn, Bp, DHn, DHn, As, Bs, acc);

    const int lane = threadIdx.x & 31, warp = threadIdx.x >> 5;
    const int wy = warp >> 2, wx = warp & 3;
    const int lg = lane >> 2, lt = lane & 3;
    const bool isK = (z==1 || z==4);

    #pragma unroll
    for (int fm=0; fm<4; fm++){
        #pragma unroll
        for (int fn=0; fn<4; fn++){
            int r = wy*64 + fm*16 + lg;
            int c = wx*32 + fn*8 + lt*2;
            #pragma unroll
            for (int q=0; q<4; q++){
                int m = m0 + r + (q>=2 ? 8 : 0);
                int n = n0 + c + (q&1);
                float v = acc[fm][fn][q] + bi[n];
                int b = m>>9, s = m&511, h = n>>6, d = n&63;
                if (isK) dst[(((size_t)(b*8+h))*64 + d)*512 + s] = v;
                else     dst[(((size_t)(b*8+h))*512 + s)*64 + d] = v;
            }
        }
    }
}

// =================== scores: batched Q @ K^T -> logits (into aw slots) ===================
__global__ void __launch_bounds__(256,2) score_k(
    const float* __restrict__ q1, const float* __restrict__ k1,
    const float* __restrict__ q2, const float* __restrict__ k2,
    float* __restrict__ aw_l, float* __restrict__ aw_g)
{
    __shared__ unsigned As[128][PADA];
    __shared__ unsigned Bs[16][136];

    const int z = blockIdx.z;
    const int zb = z & 127, sel = z >> 7;
    const int m0 = blockIdx.y*128, n0 = blockIdx.x*128;
    const float* qp = (sel ? q2 : q1) + (size_t)zb*Sn*HDn + (size_t)m0*HDn;
    const float* kp = (sel ? k2 : k1) + (size_t)zb*Sn*HDn + n0;
    float* C = (sel ? aw_g : aw_l) + (size_t)zb*Sn*Sn;

    float acc[4][4][4];
    #pragma unroll
    for (int i=0;i<4;i++) for (int j=0;j<4;j++) for (int r=0;r<4;r++) acc[i][j][r]=0.f;

    gemm_core_tf32<128>(qp, HDn, kp, Sn, HDn, As, Bs, acc);

    const int lane = threadIdx.x & 31, warp = threadIdx.x >> 5;
    const int wy = warp >> 2, wx = warp & 3;
    const int lg = lane >> 2, lt = lane & 3;

    #pragma unroll
    for (int fm=0; fm<4; fm++){
        #pragma unroll
        for (int fn=0; fn<4; fn++){
            int r = wy*64 + fm*16 + lg;
            int c = wx*32 + fn*8 + lt*2;
            #pragma unroll
            for (int q=0; q<4; q++){
                int m = m0 + r + (q>=2 ? 8 : 0);
                int n = n0 + c + (q&1);
                C[(size_t)m*Sn + n] = acc[fm][fn][q];
            }
        }
    }
}

// =================== softmax (in-place on aw slots) ===================
__global__ void __launch_bounds__(128) softmax_k(
    float* __restrict__ aw_l, float* __restrict__ aw_g,
    const float* __restrict__ mask,
    const float* __restrict__ adjoin, const float* __restrict__ dist)
{
    __shared__ float red[4];
    const int t = threadIdx.x;
    const int zi = blockIdx.y;
    const int mode = zi >> 7;            // 0: local, 1: global
    const int zb = zi & 127;
    const int b = zb >> 3;
    const int i = blockIdx.x;

    float* row = (mode ? aw_g : aw_l) + ((size_t)zb*Sn + i)*Sn;
    const float* erow = (mode ? dist : adjoin) + ((size_t)b*Sn + i)*Sn;
    const float* mrow = mask + (size_t)b*Sn;

    float lv[4];
    float lmax = -3.0e38f;
    #pragma unroll
    for (int c=0;c<4;c++){
        int j = t + c*128;
        float s = row[j];
        float logit;
        if (mode == 0){
            logit = s*0.125f + mrow[j]*(-1.0e9f) + erow[j];
        } else {
            float w = erow[j];
            float r = 3.7182818284590452f / (1.f + expf(1.f - w));
            logit = fmaxf(s, 0.f)*r*0.125f + mrow[j]*(-1.0e9f);
        }
        lv[c] = logit;
        lmax = fmaxf(lmax, logit);
    }
    #pragma unroll
    for (int o=16;o>0;o>>=1) lmax = fmaxf(lmax, __shfl_xor_sync(0xffffffffu, lmax, o));
    if ((t & 31) == 0) red[t>>5] = lmax;
    __syncthreads();
    float gmax = fmaxf(fmaxf(red[0],red[1]), fmaxf(red[2],red[3]));
    __syncthreads();

    float lsum = 0.f;
    #pragma unroll
    for (int c=0;c<4;c++){ lv[c] = expf(lv[c]-gmax); lsum += lv[c]; }
    #pragma unroll
    for (int o=16;o>0;o>>=1) lsum += __shfl_xor_sync(0xffffffffu, lsum, o);
    if ((t & 31) == 0) red[t>>5] = lsum;
    __syncthreads();
    float inv = 1.f / (red[0]+red[1]+red[2]+red[3]);

    #pragma unroll
    for (int c=0;c<4;c++){
        int j = t + c*128;
        row[j] = lv[c]*inv;
    }
}

// =================== AV: batched aw @ V, scatter to (B,S,512) ===================
__global__ void __launch_bounds__(128,4) av_k(
    const float* __restrict__ aw_l, const float* __restrict__ aw_g,
    const float* __restrict__ v1, const float* __restrict__ v2,
    float* __restrict__ av1, float* __restrict__ av2)
{
    __shared__ unsigned As[128][PADA];
    __shared__ unsigned Bs[16][72];

    const int z = blockIdx.z;
    const int zb = z & 127, sel = z >> 7;
    const int m0 = blockIdx.y*128;
    const float* A = (sel ? aw_g : aw_l) + (size_t)zb*Sn*Sn + (size_t)m0*Sn;
    const float* Bp = (sel ? v2 : v1) + (size_t)zb*Sn*HDn;
    float* dst = sel ? av2 : av1;
    const int b = zb >> 3, h = zb & 7;

    float acc[4][4][4];
    #pragma unroll
    for (int i=0;i<4;i++) for (int j=0;j<4;j++) for (int r=0;r<4;r++) acc[i][j][r]=0.f;

    gemm_core_tf32<64>(A, Sn, Bp, HDn, Sn, As, Bs, acc);

    const int lane = threadIdx.x & 31, warp = threadIdx.x >> 5;
    const int wy = warp >> 1, wx = warp & 1;
    const int lg = lane >> 2, lt = lane & 3;

    #pragma unroll
    for (int fm=0; fm<4; fm++){
        #pragma unroll
        for (int fn=0; fn<4; fn++){
            int r = wy*64 + fm*16 + lg;
            int c = wx*32 + fn*8 + lt*2;
            #pragma unroll
            for (int q=0; q<4; q++){
                int m = m0 + r + (q>=2 ? 8 : 0);
                int n = c + (q&1);
                dst[((size_t)b*Sn + m)*DHn + h*HDn + n] = acc[fm][fn][q];
            }
        }
    }
}

// =================== generic linear: C = A@B + bias (EPI1 = GELU) ===================
template<int EPI>
__global__ void __launch_bounds__(256,2) lin_k(
    const float* __restrict__ A, int lda,
    const float* __restrict__ Bw, int ldb,
    const float* __restrict__ bias,
    float* __restrict__ C, int ldc, int coff, int K)
{
    __shared__ unsigned As[128][PADA];
    __shared__ unsigned Bs[16][136];

    const int m0 = blockIdx.y*128, n0 = blockIdx.x*128;
    const float* Ap = A + (size_t)m0*lda;
    const float* Bp = Bw + n0;

    float acc[4][4][4];
    #pragma unroll
    for (int i=0;i<4;i++) for (int j=0;j<4;j++) for (int r=0;r<4;r++) acc[i][j][r]=0.f;

    gemm_core_tf32<128>(Ap, lda, Bp, ldb, K, As, Bs, acc);

    const int lane = threadIdx.x & 31, warp = threadIdx.x >> 5;
    const int wy = warp >> 2, wx = warp & 3;
    const int lg = lane >> 2, lt = lane & 3;

    #pragma unroll
    for (int fm=0; fm<4; fm++){
        #pragma unroll
        for (int fn=0; fn<4; fn++){
            int r = wy*64 + fm*16 + lg;
            int c = wx*32 + fn*8 + lt*2;
            #pragma unroll
            for (int q=0; q<4; q++){
                int m = m0 + r + (q>=2 ? 8 : 0);
                int n = n0 + c + (q&1);
                float v = acc[fm][fn][q] + bias[n];
                if (EPI == 1) v = gelu_f(v);
                C[(size_t)m*ldc + coff + n] = v;
            }
        }
    }
}

// ---------------- fused add + LayerNorm ----------------
__global__ void __launch_bounds__(256) add_ln_k(
    const float* __restrict__ a, const float* __restrict__ r,
    const float* __restrict__ g, const float* __restrict__ be,
    float* __restrict__ out)
{
    __shared__ float red[8];
    const int row = blockIdx.x;
    const int t = threadIdx.x;
    const float* ar = a + (size_t)row*Dn;
    const float* rr = r + (size_t)row*Dn;

    float vals[4];
    float s = 0.f;
    #pragma unroll
    for (int c=0;c<4;c++){
        float x = ar[t + c*256] + rr[t + c*256];
        vals[c] = x; s += x;
    }
    #pragma unroll
    for (int o=16;o>0;o>>=1) s += __shfl_xor_sync(0xffffffffu, s, o);
    if ((t & 31) == 0) red[t>>5] = s;
    __syncthreads();
    float tot = 0.f;
    #pragma unroll
    for (int w=0;w<8;w++) tot += red[w];
    float mean = tot * (1.f/1024.f);
    __syncthreads();

    float sq = 0.f;
    #pragma unroll
    for (int c=0;c<4;c++){ float dx = vals[c]-mean; sq += dx*dx; }
    #pragma unroll
    for (int o=16;o>0;o>>=1) sq += __shfl_xor_sync(0xffffffffu, sq, o);
    if ((t & 31) == 0) red[t>>5] = sq;
    __syncthreads();
    float vtot = 0.f;
    #pragma unroll
    for (int w=0;w<8;w++) vtot += red[w];
    float invstd = rsqrtf(vtot*(1.f/1024.f) + 1e-5f);

    #pragma unroll
    for (int c=0;c<4;c++){
        int dd = t + c*256;
        out[(size_t)row*Dn + dd] = (vals[c]-mean)*invstd*g[dd] + be[dd];
    }
}

// ---------------- launch ----------------
extern "C" void kernel_launch(void* const* d_in, const int* in_sizes, int n_in,
                              void* d_out, int out_size)
{
    const float* x      = (const float*)d_in[0];
    const float* mask   = (const float*)d_in[2];
    const float* adjoin = (const float*)d_in[3];
    const float* dist   = (const float*)d_in[4];
    const float* wq1=(const float*)d_in[5],  *bq1=(const float*)d_in[6];
    const float* wk1=(const float*)d_in[7],  *bk1=(const float*)d_in[8];
    const float* wv1=(const float*)d_in[9],  *bv1=(const float*)d_in[10];
    const float* wo1=(const float*)d_in[11], *bo1=(const float*)d_in[12];
    const float* wq2=(const float*)d_in[13], *bq2=(const float*)d_in[14];
    const float* wk2=(const float*)d_in[15], *bk2=(const float*)d_in[16];
    const float* wv2=(const float*)d_in[17], *bv2=(const float*)d_in[18];
    const float* wo2=(const float*)d_in[19], *bo2=(const float*)d_in[20];
    const float* wff1=(const float*)d_in[21], *bff1=(const float*)d_in[22];
    const float* wff2=(const float*)d_in[23], *bff2=(const float*)d_in[24];
    const float* ln1g=(const float*)d_in[25], *ln1b=(const float*)d_in[26];
    const float* ln2g=(const float*)d_in[27], *ln2b=(const float*)d_in[28];

    float* out2 = (float*)d_out;                         // (B,S,D)
    float* aw_l = out2 + (size_t)BSn*Dn;                 // (B,H,S,S)
    float* aw_g = aw_l + (size_t)Bn*Hn*Sn*Sn;            // (B,H,S,S)

    float *q1,*k1,*v1,*q2,*k2,*v2,*av1,*av2,*attn,*out1,*hid,*ffn;
    cudaGetSymbolAddress((void**)&q1, g_q1);
    cudaGetSymbolAddress((void**)&k1, g_k1);
    cudaGetSymbolAddress((void**)&v1, g_v1);
    cudaGetSymbolAddress((void**)&q2, g_q2);
    cudaGetSymbolAddress((void**)&k2, g_k2);
    cudaGetSymbolAddress((void**)&v2, g_v2);
    cudaGetSymbolAddress((void**)&av1, g_av1);
    cudaGetSymbolAddress((void**)&av2, g_av2);
    cudaGetSymbolAddress((void**)&attn, g_attn);
    cudaGetSymbolAddress((void**)&out1, g_out1);
    cudaGetSymbolAddress((void**)&hid, g_hid);
    cudaGetSymbolAddress((void**)&ffn, g_ffn);

    // QKV: 6 fused batched GEMMs (K stored transposed)
    dim3 gqkv(4, 64, 6);
    qkv_k<<<gqkv,256>>>(x, wq1,wk1,wv1,wq2,wk2,wv2,
                           bq1,bk1,bv1,bq2,bk2,bv2,
                           q1,k1,v1,q2,k2,v2);

    // scores -> logits written into aw slots of d_out
    dim3 gsc(4, 4, 256);
    score_k<<<gsc,256>>>(q1,k1,q2,k2, aw_l, aw_g);

    // softmax in place
    dim3 gsm(Sn, 256);
    softmax_k<<<gsm,128>>>(aw_l, aw_g, mask, adjoin, dist);

    // AV batched GEMM -> (B,S,512) concat-ready
    dim3 gav(1, 4, 256);
    av_k<<<gav,128>>>(aw_l, aw_g, v1, v2, av1, av2);

    // output projections -> concat into g_attn (B,S,1024)
    dim3 gop(4, 64);
    lin_k<0><<<gop,256>>>(av1, DHn, wo1, DHn, bo1, attn, Dn, 0,   DHn);
    lin_k<0><<<gop,256>>>(av2, DHn, wo2, DHn, bo2, attn, Dn, DHn, DHn);

    // LN1(x + attn)
    add_ln_k<<<BSn,256>>>(x, attn, ln1g, ln1b, out1);

    // FFN
    dim3 gff1(32, 64);
    lin_k<1><<<gff1,256>>>(out1, Dn, wff1, DFFn, bff1, hid, DFFn, 0, Dn);
    dim3 gff2(8, 64);
    lin_k<0><<<gff2,256>>>(hid, DFFn, wff2, Dn, bff2, ffn, Dn, 0, DFFn);

    // LN2(out1 + ffn) -> out2
    add_ln_k<<<BSn,256>>>(out1, ffn, ln2g, ln2b, out2);
}

// round 7
// speedup vs baseline: 4.6536x; 1.3054x over previous
#include <cuda_runtime.h>
#include <math.h>
#include <stdint.h>

#define Bn   16
#define Sn   512
#define Dn   1024
#define Hn   8
#define DHn  512
#define HDn  64
#define DFFn 4096
#define BSn  (Bn*Sn)   // 8192

// ---------------- scratch (static device globals; no allocation) ----------------
__device__ float g_q1[Bn*Hn*Sn*HDn];
__device__ float g_k1[Bn*Hn*Sn*HDn];   // stored transposed: (B,H,64,S)
__device__ float g_v1[Bn*Hn*Sn*HDn];
__device__ float g_q2[Bn*Hn*Sn*HDn];
__device__ float g_k2[Bn*Hn*Sn*HDn];   // transposed
__device__ float g_v2[Bn*Hn*Sn*HDn];
__device__ float g_av1[BSn*DHn];
__device__ float g_av2[BSn*DHn];
__device__ float g_attn[BSn*Dn];
__device__ float g_out1[BSn*Dn];
__device__ float g_hid[(size_t)BSn*DFFn];
__device__ float g_ffn[BSn*Dn];

__device__ __forceinline__ float gelu_f(float x){
    return 0.5f * x * (1.0f + erff(x * 0.70710678118654752440f));
}
__device__ __forceinline__ unsigned f2tf(float x){
    unsigned u; asm("cvt.rna.tf32.f32 %0, %1;" : "=r"(u) : "f"(x)); return u;
}

#define MMA_TF32(acc, af, bf) \
    asm volatile( \
        "mma.sync.aligned.m16n8k8.row.col.f32.tf32.tf32.f32 " \
        "{%0,%1,%2,%3}, {%4,%5,%6,%7}, {%8,%9}, {%0,%1,%2,%3};" \
        : "+f"((acc)[0]), "+f"((acc)[1]), "+f"((acc)[2]), "+f"((acc)[3]) \
        : "r"((af)[0]), "r"((af)[1]), "r"((af)[2]), "r"((af)[3]), \
          "r"((bf)[0]), "r"((bf)[1]))

// =================== pipelined TF32 GEMM core (128x128x16, 256 thr) ===================
#define PADA 20

__device__ __forceinline__ void gemm_core_pipe(
    const float* __restrict__ A, int lda,
    const float* __restrict__ Bw, int ldb,
    int K,
    unsigned (*As)[PADA], unsigned (*Bs)[136],
    float (&acc)[4][4][4])
{
    const int tid  = threadIdx.x;
    const int lane = tid & 31;
    const int warp = tid >> 5;
    const int wy = warp >> 2, wx = warp & 3;
    const int lg = lane >> 2, lt = lane & 3;

    // prefetch slab 0 into registers
    float4 ra[2], rb[2];
    #pragma unroll
    for (int it = 0; it < 2; it++) {
        int l = tid + it*256;
        ra[it] = *(const float4*)(A + (size_t)(l>>2)*lda + (l&3)*4);
        rb[it] = *(const float4*)(Bw + (size_t)(l>>5)*ldb + (l&31)*4);
    }

    for (int k0 = 0; k0 < K; k0 += 16) {
        // commit registers -> smem (cvt to tf32 here, RNA)
        #pragma unroll
        for (int it = 0; it < 2; it++) {
            int l = tid + it*256;
            int row = l >> 2, kq = l & 3;
            uint4 t;
            t.x = f2tf(ra[it].x); t.y = f2tf(ra[it].y);
            t.z = f2tf(ra[it].z); t.w = f2tf(ra[it].w);
            *(uint4*)(&As[row][kq*4]) = t;
            int kk = l >> 5, nq = l & 31;
            uint4 u;
            u.x = f2tf(rb[it].x); u.y = f2tf(rb[it].y);
            u.z = f2tf(rb[it].z); u.w = f2tf(rb[it].w);
            *(uint4*)(&Bs[kk][nq*4]) = u;
        }
        __syncthreads();

        // issue next slab's loads (overlap with MMA below)
        if (k0 + 16 < K) {
            #pragma unroll
            for (int it = 0; it < 2; it++) {
                int l = tid + it*256;
                ra[it] = *(const float4*)(A + (size_t)(l>>2)*lda + k0 + 16 + (l&3)*4);
                rb[it] = *(const float4*)(Bw + (size_t)(k0 + 16 + (l>>5))*ldb + (l&31)*4);
            }
        }

        #pragma unroll
        for (int ks = 0; ks < 2; ks++) {
            const int kb = ks*8;
            unsigned af[4][4], bf[4][2];
            #pragma unroll
            for (int fm = 0; fm < 4; fm++) {
                int rbw = wy*64 + fm*16 + lg;
                af[fm][0] = As[rbw  ][kb+lt];
                af[fm][1] = As[rbw+8][kb+lt];
                af[fm][2] = As[rbw  ][kb+4+lt];
                af[fm][3] = As[rbw+8][kb+4+lt];
            }
            #pragma unroll
            for (int fn = 0; fn < 4; fn++) {
                int cb = wx*32 + fn*8 + lg;
                bf[fn][0] = Bs[kb+lt  ][cb];
                bf[fn][1] = Bs[kb+4+lt][cb];
            }
            #pragma unroll
            for (int fm = 0; fm < 4; fm++)
                #pragma unroll
                for (int fn = 0; fn < 4; fn++)
                    MMA_TF32(acc[fm][fn], af[fm], bf[fn]);
        }
        __syncthreads();
    }
}

// =================== QKV: 6 batched GEMMs, scatter epilogue ===================
__global__ void __launch_bounds__(256,2) qkv_k(
    const float* __restrict__ x,
    const float* w0, const float* w1, const float* w2,
    const float* w3, const float* w4, const float* w5,
    const float* b0, const float* b1, const float* b2,
    const float* b3, const float* b4, const float* b5,
    float* o0, float* o1, float* o2, float* o3, float* o4, float* o5)
{
    __shared__ unsigned As[128][PADA];
    __shared__ unsigned Bs[16][136];

    const int z = blockIdx.z;
    const float* W; const float* bi; float* dst;
    switch (z) {
        case 0: W=w0; bi=b0; dst=o0; break;
        case 1: W=w1; bi=b1; dst=o1; break;
        case 2: W=w2; bi=b2; dst=o2; break;
        case 3: W=w3; bi=b3; dst=o3; break;
        case 4: W=w4; bi=b4; dst=o4; break;
        default:W=w5; bi=b5; dst=o5; break;
    }
    const int m0 = blockIdx.y*128, n0 = blockIdx.x*128;
    const float* A = x + (z>=3 ? DHn : 0) + (size_t)m0*Dn;
    const float* Bp = W + n0;

    float acc[4][4][4];
    #pragma unroll
    for (int i=0;i<4;i++) for (int j=0;j<4;j++) for (int r=0;r<4;r++) acc[i][j][r]=0.f;

    gemm_core_pipe(A, Dn, Bp, DHn, DHn, As, Bs, acc);

    const int lane = threadIdx.x & 31, warp = threadIdx.x >> 5;
    const int wy = warp >> 2, wx = warp & 3;
    const int lg = lane >> 2, lt = lane & 3;
    const bool isK = (z==1 || z==4);

    #pragma unroll
    for (int fm=0; fm<4; fm++){
        #pragma unroll
        for (int fn=0; fn<4; fn++){
            int r = wy*64 + fm*16 + lg;
            int c = wx*32 + fn*8 + lt*2;
            #pragma unroll
            for (int q=0; q<4; q++){
                int m = m0 + r + (q>=2 ? 8 : 0);
                int n = n0 + c + (q&1);
                float v = acc[fm][fn][q] + bi[n];
                int b = m>>9, s = m&511, h = n>>6, d = n&63;
                if (isK) dst[(((size_t)(b*8+h))*64 + d)*512 + s] = v;
                else     dst[(((size_t)(b*8+h))*512 + s)*64 + d] = v;
            }
        }
    }
}

// =================== fused attention: score + softmax + aw write + AV ===================
// m-tile = 64 queries; full 512-key logit rows live in smem.
// grid (8 m-tiles, 256 = sel*128 + bh), 256 threads.
#define SLD 516   // sL row stride in floats (516 % 32 == 4 -> conflict-free col reads)

__global__ void __launch_bounds__(256,1) fattn_k(
    const float* __restrict__ q1, const float* __restrict__ k1, const float* __restrict__ v1,
    const float* __restrict__ q2, const float* __restrict__ k2, const float* __restrict__ v2,
    const float* __restrict__ mask, const float* __restrict__ adjoin, const float* __restrict__ dist,
    float* __restrict__ aw_l, float* __restrict__ aw_g,
    float* __restrict__ av1, float* __restrict__ av2)
{
    extern __shared__ char smem_raw[];
    float* sL = (float*)smem_raw;                                        // [64][SLD]
    unsigned (*sQ)[68]  = (unsigned(*)[68]) (smem_raw + 64*SLD*4);       // [64][68]
    unsigned (*sB)[136] = (unsigned(*)[136])(smem_raw + 64*SLD*4 + 64*68*4); // [16][136]

    const int tid = threadIdx.x, lane = tid & 31, warp = tid >> 5;
    const int lg = lane >> 2, lt = lane & 3;
    const int zi = blockIdx.y;
    const int sel = zi >> 7, zb = zi & 127;
    const int b = zb >> 3, h = zb & 7;
    const int m0 = blockIdx.x * 64;

    const float* q  = (sel ? q2 : q1) + (size_t)zb*Sn*HDn;
    const float* kT = (sel ? k2 : k1) + (size_t)zb*HDn*Sn;   // (64,512)
    const float* v  = (sel ? v2 : v1) + (size_t)zb*Sn*HDn;
    float* aw = (sel ? aw_g : aw_l) + (size_t)zb*Sn*Sn;
    float* av = sel ? av2 : av1;
    const float* extra = (sel ? dist : adjoin) + (size_t)b*Sn*Sn;
    const float* mrow  = mask + (size_t)b*Sn;

    // ---- Phase 1: Q tile (64x64) -> sQ as tf32 ----
    #pragma unroll
    for (int it = 0; it < 4; it++) {
        int l = tid + it*256;            // float4 index over 64x16
        int row = l >> 4, dq = l & 15;
        float4 a = *(const float4*)(q + (size_t)(m0+row)*HDn + dq*4);
        uint4 t;
        t.x = f2tf(a.x); t.y = f2tf(a.y); t.z = f2tf(a.z); t.w = f2tf(a.w);
        *(uint4*)(&sQ[row][dq*4]) = t;
    }

    // ---- Phase 2: scores (64 x 512) -> sL (with mask/extra transforms) ----
    {
        const int wy = warp >> 2, wx = warp & 3;   // 2 x 4 warp grid
        for (int n0 = 0; n0 < 512; n0 += 128) {
            float acc[2][4][4];
            #pragma unroll
            for (int i=0;i<2;i++) for (int j=0;j<4;j++) for (int r=0;r<4;r++) acc[i][j][r]=0.f;

            float4 rk[2];
            #pragma unroll
            for (int it = 0; it < 2; it++) {
                int l = tid + it*256;
                rk[it] = *(const float4*)(kT + (size_t)(l>>5)*Sn + n0 + (l&31)*4);
            }
            for (int kc = 0; kc < 4; kc++) {
                #pragma unroll
                for (int it = 0; it < 2; it++) {
                    int l = tid + it*256;
                    int kk = l >> 5, nq = l & 31;
                    uint4 t;
                    t.x = f2tf(rk[it].x); t.y = f2tf(rk[it].y);
                    t.z = f2tf(rk[it].z); t.w = f2tf(rk[it].w);
                    *(uint4*)(&sB[kk][nq*4]) = t;
                }
                __syncthreads();
                if (kc < 3) {
                    #pragma unroll
                    for (int it = 0; it < 2; it++) {
                        int l = tid + it*256;
                        rk[it] = *(const float4*)(kT + (size_t)(kc*16 + 16 + (l>>5))*Sn + n0 + (l&31)*4);
                    }
                }
                #pragma unroll
                for (int ks = 0; ks < 2; ks++) {
                    int kb = kc*16 + ks*8;      // sQ column
                    int sb = ks*8;              // sB row
                    unsigned af[2][4], bf[4][2];
                    #pragma unroll
                    for (int fm = 0; fm < 2; fm++) {
                        int rb = wy*32 + fm*16 + lg;
                        af[fm][0] = sQ[rb  ][kb+lt];
                        af[fm][1] = sQ[rb+8][kb+lt];
                        af[fm][2] = sQ[rb  ][kb+4+lt];
                        af[fm][3] = sQ[rb+8][kb+4+lt];
                    }
                    #pragma unroll
                    for (int fn = 0; fn < 4; fn++) {
                        int cb = wx*32 + fn*8 + lg;
                        bf[fn][0] = sB[sb+lt  ][cb];
                        bf[fn][1] = sB[sb+4+lt][cb];
                    }
                    #pragma unroll
                    for (int fm = 0; fm < 2; fm++)
                        #pragma unroll
                        for (int fn = 0; fn < 4; fn++)
                            MMA_TF32(acc[fm][fn], af[fm], bf[fn]);
                }
                __syncthreads();
            }
            // epilogue: logits -> sL
            #pragma unroll
            for (int fm = 0; fm < 2; fm++) {
                #pragma unroll
                for (int fn = 0; fn < 4; fn++) {
                    #pragma unroll
                    for (int q4 = 0; q4 < 4; q4++) {
                        int r = wy*32 + fm*16 + lg + ((q4>=2) ? 8 : 0);
                        int c = wx*32 + fn*8 + lt*2 + (q4&1);
                        int j = n0 + c;
                        float s = acc[fm][fn][q4];
                        float logit;
                        if (sel == 0) {
                            logit = s*0.125f + mrow[j]*(-1.0e9f)
                                  + extra[(size_t)(m0+r)*Sn + j];
                        } else {
                            float w  = extra[(size_t)(m0+r)*Sn + j];
                            float rs = 3.7182818284590452f / (1.f + expf(1.f - w));
                            logit = fmaxf(s, 0.f)*rs*0.125f + mrow[j]*(-1.0e9f);
                        }
                        sL[r*SLD + j] = logit;
                    }
                }
            }
        }
    }
    __syncthreads();

    // ---- Phase 3: softmax per row (warp handles 8 rows); write aw ----
    for (int rr = 0; rr < 8; rr++) {
        int r = warp*8 + rr;
        float4* rowp = (float4*)(sL + (size_t)r*SLD);
        float4 rv[4];
        float lmax = -3.0e38f;
        #pragma unroll
        for (int it = 0; it < 4; it++) {
            float4 v4 = rowp[it*32 + lane];
            rv[it] = v4;
            lmax = fmaxf(lmax, fmaxf(fmaxf(v4.x, v4.y), fmaxf(v4.z, v4.w)));
        }
        #pragma unroll
        for (int o = 16; o > 0; o >>= 1)
            lmax = fmaxf(lmax, __shfl_xor_sync(0xffffffffu, lmax, o));
        float sum = 0.f;
        #pragma unroll
        for (int it = 0; it < 4; it++) {
            rv[it].x = expf(rv[it].x - lmax);
            rv[it].y = expf(rv[it].y - lmax);
            rv[it].z = expf(rv[it].z - lmax);
            rv[it].w = expf(rv[it].w - lmax);
            sum += rv[it].x + rv[it].y + rv[it].z + rv[it].w;
        }
        #pragma unroll
        for (int o = 16; o > 0; o >>= 1)
            sum += __shfl_xor_sync(0xffffffffu, sum, o);
        float inv = 1.f / sum;
        float4* awp = (float4*)(aw + (size_t)(m0+r)*Sn);
        #pragma unroll
        for (int it = 0; it < 4; it++) {
            rv[it].x *= inv; rv[it].y *= inv; rv[it].z *= inv; rv[it].w *= inv;
            rowp[it*32 + lane] = rv[it];
            awp[it*32 + lane]  = rv[it];
        }
    }
    __syncthreads();

    // ---- Phase 4: AV = probs(64x512) @ V(512x64) ----
    {
        const int wy4 = warp >> 1, wx4 = warp & 1;   // 4 x 2 warp grid
        float acc2[4][4];
        #pragma unroll
        for (int j=0;j<4;j++) for (int r=0;r<4;r++) acc2[j][r]=0.f;

        float4 rvv;
        { int kk = tid >> 4, dq = tid & 15;
          rvv = *(const float4*)(v + (size_t)kk*HDn + dq*4); }
        for (int kc = 0; kc < 32; kc++) {
            { int kk = tid >> 4, dq = tid & 15;
              uint4 t;
              t.x = f2tf(rvv.x); t.y = f2tf(rvv.y);
              t.z = f2tf(rvv.z); t.w = f2tf(rvv.w);
              *(uint4*)(&sB[kk][dq*4]) = t; }
            __syncthreads();
            if (kc < 31) {
                int kk = tid >> 4, dq = tid & 15;
                rvv = *(const float4*)(v + (size_t)(kc*16 + 16 + kk)*HDn + dq*4);
            }
            #pragma unroll
            for (int ks = 0; ks < 2; ks++) {
                int kb = kc*16 + ks*8;    // sL column
                int sb = ks*8;            // sB row
                int rb = wy4*16 + lg;
                unsigned af[4];
                af[0] = f2tf(sL[(size_t) rb   *SLD + kb+lt]);
                af[1] = f2tf(sL[(size_t)(rb+8)*SLD + kb+lt]);
                af[2] = f2tf(sL[(size_t) rb   *SLD + kb+4+lt]);
                af[3] = f2tf(sL[(size_t)(rb+8)*SLD + kb+4+lt]);
                unsigned bf[4][2];
                #pragma unroll
                for (int fn = 0; fn < 4; fn++) {
                    int cb = wx4*32 + fn*8 + lg;
                    bf[fn][0] = sB[sb+lt  ][cb];
                    bf[fn][1] = sB[sb+4+lt][cb];
                }
                #pragma unroll
                for (int fn = 0; fn < 4; fn++)
                    MMA_TF32(acc2[fn], af, bf[fn]);
            }
            __syncthreads();
        }
        #pragma unroll
        for (int fn = 0; fn < 4; fn++) {
            #pragma unroll
            for (int q4 = 0; q4 < 4; q4++) {
                int r = wy4*16 + lg + ((q4>=2) ? 8 : 0);
                int c = wx4*32 + fn*8 + lt*2 + (q4&1);
                av[((size_t)b*Sn + m0 + r)*DHn + h*HDn + c] = acc2[fn][q4];
            }
        }
    }
}

// =================== generic linear: C = A@B + bias (EPI1 = GELU) ===================
template<int EPI>
__global__ void __launch_bounds__(256,2) lin_k(
    const float* __restrict__ A, int lda,
    const float* __restrict__ Bw, int ldb,
    const float* __restrict__ bias,
    float* __restrict__ C, int ldc, int coff, int K)
{
    __shared__ unsigned As[128][PADA];
    __shared__ unsigned Bs[16][136];

    const int m0 = blockIdx.y*128, n0 = blockIdx.x*128;
    const float* Ap = A + (size_t)m0*lda;
    const float* Bp = Bw + n0;

    float acc[4][4][4];
    #pragma unroll
    for (int i=0;i<4;i++) for (int j=0;j<4;j++) for (int r=0;r<4;r++) acc[i][j][r]=0.f;

    gemm_core_pipe(Ap, lda, Bp, ldb, K, As, Bs, acc);

    const int lane = threadIdx.x & 31, warp = threadIdx.x >> 5;
    const int wy = warp >> 2, wx = warp & 3;
    const int lg = lane >> 2, lt = lane & 3;

    #pragma unroll
    for (int fm=0; fm<4; fm++){
        #pragma unroll
        for (int fn=0; fn<4; fn++){
            int r = wy*64 + fm*16 + lg;
            int c = wx*32 + fn*8 + lt*2;
            #pragma unroll
            for (int q=0; q<4; q++){
                int m = m0 + r + (q>=2 ? 8 : 0);
                int n = n0 + c + (q&1);
                float v = acc[fm][fn][q] + bias[n];
                if (EPI == 1) v = gelu_f(v);
                C[(size_t)m*ldc + coff + n] = v;
            }
        }
    }
}

// ---------------- fused add + LayerNorm ----------------
__global__ void __launch_bounds__(256) add_ln_k(
    const float* __restrict__ a, const float* __restrict__ r,
    const float* __restrict__ g, const float* __restrict__ be,
    float* __restrict__ out)
{
    __shared__ float red[8];
    const int row = blockIdx.x;
    const int t = threadIdx.x;
    const float* ar = a + (size_t)row*Dn;
    const float* rr = r + (size_t)row*Dn;

    float vals[4];
    float s = 0.f;
    #pragma unroll
    for (int c=0;c<4;c++){
        float x = ar[t + c*256] + rr[t + c*256];
        vals[c] = x; s += x;
    }
    #pragma unroll
    for (int o=16;o>0;o>>=1) s += __shfl_xor_sync(0xffffffffu, s, o);
    if ((t & 31) == 0) red[t>>5] = s;
    __syncthreads();
    float tot = 0.f;
    #pragma unroll
    for (int w=0;w<8;w++) tot += red[w];
    float mean = tot * (1.f/1024.f);
    __syncthreads();

    float sq = 0.f;
    #pragma unroll
    for (int c=0;c<4;c++){ float dx = vals[c]-mean; sq += dx*dx; }
    #pragma unroll
    for (int o=16;o>0;o>>=1) sq += __shfl_xor_sync(0xffffffffu, sq, o);
    if ((t & 31) == 0) red[t>>5] = sq;
    __syncthreads();
    float vtot = 0.f;
    #pragma unroll
    for (int w=0;w<8;w++) vtot += red[w];
    float invstd = rsqrtf(vtot*(1.f/1024.f) + 1e-5f);

    #pragma unroll
    for (int c=0;c<4;c++){
        int dd = t + c*256;
        out[(size_t)row*Dn + dd] = (vals[c]-mean)*invstd*g[dd] + be[dd];
    }
}

// ---------------- launch ----------------
#define FATTN_SMEM (64*SLD*4 + 64*68*4 + 16*136*4)

extern "C" void kernel_launch(void* const* d_in, const int* in_sizes, int n_in,
                              void* d_out, int out_size)
{
    const float* x      = (const float*)d_in[0];
    const float* mask   = (const float*)d_in[2];
    const float* adjoin = (const float*)d_in[3];
    const float* dist   = (const float*)d_in[4];
    const float* wq1=(const float*)d_in[5],  *bq1=(const float*)d_in[6];
    const float* wk1=(const float*)d_in[7],  *bk1=(const float*)d_in[8];
    const float* wv1=(const float*)d_in[9],  *bv1=(const float*)d_in[10];
    const float* wo1=(const float*)d_in[11], *bo1=(const float*)d_in[12];
    const float* wq2=(const float*)d_in[13], *bq2=(const float*)d_in[14];
    const float* wk2=(const float*)d_in[15], *bk2=(const float*)d_in[16];
    const float* wv2=(const float*)d_in[17], *bv2=(const float*)d_in[18];
    const float* wo2=(const float*)d_in[19], *bo2=(const float*)d_in[20];
    const float* wff1=(const float*)d_in[21], *bff1=(const float*)d_in[22];
    const float* wff2=(const float*)d_in[23], *bff2=(const float*)d_in[24];
    const float* ln1g=(const float*)d_in[25], *ln1b=(const float*)d_in[26];
    const float* ln2g=(const float*)d_in[27], *ln2b=(const float*)d_in[28];

    float* out2 = (float*)d_out;                         // (B,S,D)
    float* aw_l = out2 + (size_t)BSn*Dn;                 // (B,H,S,S)
    float* aw_g = aw_l + (size_t)Bn*Hn*Sn*Sn;            // (B,H,S,S)

    float *q1,*k1,*v1,*q2,*k2,*v2,*av1,*av2,*attn,*out1,*hid,*ffn;
    cudaGetSymbolAddress((void**)&q1, g_q1);
    cudaGetSymbolAddress((void**)&k1, g_k1);
    cudaGetSymbolAddress((void**)&v1, g_v1);
    cudaGetSymbolAddress((void**)&q2, g_q2);
    cudaGetSymbolAddress((void**)&k2, g_k2);
    cudaGetSymbolAddress((void**)&v2, g_v2);
    cudaGetSymbolAddress((void**)&av1, g_av1);
    cudaGetSymbolAddress((void**)&av2, g_av2);
    cudaGetSymbolAddress((void**)&attn, g_attn);
    cudaGetSymbolAddress((void**)&out1, g_out1);
    cudaGetSymbolAddress((void**)&hid, g_hid);
    cudaGetSymbolAddress((void**)&ffn, g_ffn);

    static int smem_set = 0;
    if (!smem_set) {
        cudaFuncSetAttribute(fattn_k, cudaFuncAttributeMaxDynamicSharedMemorySize, FATTN_SMEM);
        smem_set = 1;
    }

    // QKV: 6 fused batched GEMMs (K stored transposed)
    dim3 gqkv(4, 64, 6);
    qkv_k<<<gqkv,256>>>(x, wq1,wk1,wv1,wq2,wk2,wv2,
                           bq1,bk1,bv1,bq2,bk2,bv2,
                           q1,k1,v1,q2,k2,v2);

    // fused attention: score + softmax + aw + AV
    dim3 gfa(8, 256);
    fattn_k<<<gfa,256,FATTN_SMEM>>>(q1,k1,v1, q2,k2,v2,
                                    mask, adjoin, dist,
                                    aw_l, aw_g, av1, av2);

    // output projections -> concat into g_attn (B,S,1024)
    dim3 gop(4, 64);
    lin_k<0><<<gop,256>>>(av1, DHn, wo1, DHn, bo1, attn, Dn, 0,   DHn);
    lin_k<0><<<gop,256>>>(av2, DHn, wo2, DHn, bo2, attn, Dn, DHn, DHn);

    // LN1(x + attn)
    add_ln_k<<<BSn,256>>>(x, attn, ln1g, ln1b, out1);

    // FFN
    dim3 gff1(32, 64);
    lin_k<1><<<gff1,256>>>(out1, Dn, wff1, DFFn, bff1, hid, DFFn, 0, Dn);
    dim3 gff2(8, 64);
    lin_k<0><<<gff2,256>>>(hid, DFFn, wff2, Dn, bff2, ffn, Dn, 0, DFFn);

    // LN2(out1 + ffn) -> out2
    add_ln_k<<<BSn,256>>>(out1, ffn, ln2g, ln2b, out2);
}